// round 11
// baseline (speedup 1.0000x reference)
#include <cuda_runtime.h>
#include <cuda_bf16.h>
#include <cstdint>

#define NN   16384
#define NE   262144
#define NG   16
#define CIN  128
#define CHID 256
#define CLAT 64

// ---- scratch (device globals; no allocation allowed) ----
__device__ float g_deg[NN];
__device__ float g_dinv[NN];
__device__ float g_aggx[NN * CIN];
__device__ float g_h[NN * CHID];
__device__ float g_wT[CIN * CHID];
__device__ float g_linT[CHID * CLAT];
__device__ float g_zsum[NG * CLAT];
__device__ float g_cnt[NG];
__device__ float g_gdec[NG * CIN];
__device__ __nv_bfloat16 g_zhi[NN * CLAT];   // bf16 hi part of z_node
__device__ __nv_bfloat16 g_zlo[NN * CLAT];   // bf16 lo part of z_node
__device__ int g_off[NN + 1];                // CSR offsets (in-edges per node)
__device__ int g_cur[NN];                    // placement cursors
__device__ int g_srcs[NE];                   // CSR source-node list

// ---------------------------------------------------------
__global__ void k_init() {
    int i = blockIdx.x * blockDim.x + threadIdx.x;
    if (i < NN) g_deg[i] = 1.0f;
    if (i < NG * CLAT) g_zsum[i] = 0.0f;
    if (i < NG) g_cnt[i] = 0.0f;
}

__global__ void k_deg(const int* __restrict__ ei) {
    int e = blockIdx.x * blockDim.x + threadIdx.x;
    if (e < NE) atomicAdd(&g_deg[ei[NE + e]], 1.0f);
}

__global__ void k_dinv() {
    int i = blockIdx.x * blockDim.x + threadIdx.x;
    if (i < NN) g_dinv[i] = rsqrtf(g_deg[i]);
}

// CSR offsets from degrees (deg-1 = in-edge count). One block, 1024 threads.
__global__ void k_prefix() {
    __shared__ int ssum[1024];
    int t = threadIdx.x;
    int base = t * 16;
    int loc[16];
    int s = 0;
#pragma unroll
    for (int i = 0; i < 16; i++) {
        loc[i] = s;
        s += (int)g_deg[base + i] - 1;
    }
    ssum[t] = s;
    __syncthreads();
    for (int d = 1; d < 1024; d <<= 1) {
        int v = (t >= d) ? ssum[t - d] : 0;
        __syncthreads();
        ssum[t] += v;
        __syncthreads();
    }
    int excl = (t == 0) ? 0 : ssum[t - 1];
#pragma unroll
    for (int i = 0; i < 16; i++) {
        int o = excl + loc[i];
        g_off[base + i] = o;
        g_cur[base + i] = o;
    }
    if (t == 1023) g_off[NN] = ssum[1023];
}

// place each edge's source into its destination's CSR slot
__global__ void k_place(const int* __restrict__ ei) {
    int e = blockIdx.x * blockDim.x + threadIdx.x;
    if (e < NE) {
        int col = ei[NE + e];
        int pos = atomicAdd(&g_cur[col], 1);
        g_srcs[pos] = ei[e];
    }
}

// gather aggregation: one block per node, one channel per thread. No atomics.
__global__ void __launch_bounds__(128) k_gather(const float* __restrict__ x) {
    int i = blockIdx.x;
    int t = threadIdx.x;
    float di = g_dinv[i];
    float acc = x[i * CIN + t] * (di * di);          // self-loop: 1/deg
    int beg = g_off[i], end = g_off[i + 1];
    for (int j = beg; j < end; j++) {
        int row = g_srcs[j];
        acc += x[row * CIN + t] * (di * g_dinv[row]);
    }
    g_aggx[i * CIN + t] = acc;
}

__global__ void k_wT(const float* __restrict__ gw, const float* __restrict__ lw) {
    int idx = blockIdx.x * blockDim.x + threadIdx.x;
    if (idx < CIN * CHID) {
        int h = idx >> 7, k = idx & 127;
        g_wT[k * CHID + h] = gw[idx];
    } else if (idx < CIN * CHID + CHID * CLAT) {
        int j = idx - CIN * CHID;
        int l = j >> 8, c = j & 255;
        g_linT[c * CLAT + l] = lw[j];
    }
}

__global__ void k_gcn(const float* __restrict__ gb) {
    __shared__ float sx[4][CIN];
    int i0 = blockIdx.x * 4;
    int t = threadIdx.x;
#pragma unroll
    for (int ii = 0; ii < 2; ii++) {
        int lin = t + ii * 256;
        sx[lin >> 7][lin & 127] = g_aggx[i0 * CIN + lin];
    }
    __syncthreads();
    float b = gb[t];
    float a0 = b, a1 = b, a2 = b, a3 = b;
#pragma unroll 4
    for (int k = 0; k < CIN; k++) {
        float w = g_wT[k * CHID + t];
        a0 += sx[0][k] * w;
        a1 += sx[1][k] * w;
        a2 += sx[2][k] * w;
        a3 += sx[3][k] * w;
    }
    g_h[(i0 + 0) * CHID + t] = fmaxf(a0, 0.f);
    g_h[(i0 + 1) * CHID + t] = fmaxf(a1, 0.f);
    g_h[(i0 + 2) * CHID + t] = fmaxf(a2, 0.f);
    g_h[(i0 + 3) * CHID + t] = fmaxf(a3, 0.f);
}

__global__ void k_z(const int* __restrict__ batch, const float* __restrict__ lb,
                    float* __restrict__ zout) {
    __shared__ float sA[4][CHID];
    int i0 = blockIdx.x * 4;
    int t = threadIdx.x;
#pragma unroll
    for (int ii = 0; ii < 4; ii++) {
        int lin = t + ii * 256;
        sA[lin >> 8][lin & 255] = g_h[i0 * CHID + lin];
    }
    __syncthreads();
    int j = t >> 6, c = t & 63;
    float acc = lb[c];
#pragma unroll 4
    for (int k = 0; k < CHID; k++) acc += sA[j][k] * g_linT[k * CLAT + c];
    int node = i0 + j;
    zout[node * CLAT + c] = acc;
    int b = batch[node];
    atomicAdd(&g_zsum[b * CLAT + c], acc);
    if (c == 0) atomicAdd(&g_cnt[b], 1.0f);
}

// split z into bf16 hi + bf16 lo
__global__ void k_split(const float* __restrict__ z) {
    int i = blockIdx.x * blockDim.x + threadIdx.x;
    if (i < NN * CLAT) {
        float v = z[i];
        __nv_bfloat16 h = __float2bfloat16(v);
        float lo = v - __bfloat162float(h);
        g_zhi[i] = h;
        g_zlo[i] = __float2bfloat16(lo);
    }
}

__global__ void k_graph(const float* __restrict__ dw, const float* __restrict__ db,
                        float* __restrict__ zg_out) {
    __shared__ float zg[CLAT];
    int g = blockIdx.x, t = threadIdx.x;
    if (t < CLAT) {
        float cn = fmaxf(g_cnt[g], 1.0f);
        float v = g_zsum[g * CLAT + t] / cn;
        zg[t] = v;
        zg_out[g * CLAT + t] = v;
    }
    __syncthreads();
    float acc = db[t];
#pragma unroll
    for (int l = 0; l < CLAT; l++) acc += zg[l] * dw[t * CLAT + l];
    g_gdec[g * CIN + t] = acc;
}

__global__ void k_xhat(const int* __restrict__ batch, float* __restrict__ xo) {
    int idx = blockIdx.x * blockDim.x + threadIdx.x;
    if (idx < NN * CIN) {
        int i = idx >> 7;
        xo[idx] = g_gdec[batch[i] * CIN + (idx & 127)];
    }
}

// ---------------------------------------------------------
// a_hat = sigmoid(Z Z^T): split-bf16 mma.sync m16n8k16, 3 passes.
// ---------------------------------------------------------
__device__ __forceinline__ void mma_bf16(float* c, const uint32_t* a,
                                         uint32_t b0, uint32_t b1) {
    asm volatile(
        "mma.sync.aligned.m16n8k16.row.col.f32.bf16.bf16.f32 "
        "{%0,%1,%2,%3}, {%4,%5,%6,%7}, {%8,%9}, {%0,%1,%2,%3};"
        : "+f"(c[0]), "+f"(c[1]), "+f"(c[2]), "+f"(c[3])
        : "r"(a[0]), "r"(a[1]), "r"(a[2]), "r"(a[3]), "r"(b0), "r"(b1));
}

#define PITCHB 40

__global__ void __launch_bounds__(256) k_ahat(float* __restrict__ out) {
    __shared__ __align__(16) char smbuf[4 * 128 * PITCHB * 2];  // 40960 B
    __nv_bfloat16* Ahi = (__nv_bfloat16*)smbuf;
    __nv_bfloat16* Alo = Ahi + 128 * PITCHB;
    __nv_bfloat16* Bhi = Alo + 128 * PITCHB;
    __nv_bfloat16* Blo = Bhi + 128 * PITCHB;

    const int bi = blockIdx.y, bj = blockIdx.x;
    if (bj < bi) return;
    const int tid  = threadIdx.x;
    const int w    = tid >> 5, lane = tid & 31;
    const int wm   = w & 1, wn = w >> 1;
    const int g    = lane >> 2, t = lane & 3;
    const int m0 = bi * 128, n0 = bj * 128;

    float acc[4][4][4];
#pragma unroll
    for (int a = 0; a < 4; a++)
#pragma unroll
        for (int b = 0; b < 4; b++)
#pragma unroll
            for (int r = 0; r < 4; r++) acc[a][b][r] = 0.f;

#pragma unroll
    for (int kk = 0; kk < 64; kk += 32) {
        __syncthreads();
#pragma unroll
        for (int i = 0; i < 2; i++) {
            int lin = tid + i * 256;
            int row = lin >> 2;
            int seg = (lin & 3) * 8;
            *(float4*)(Ahi + row * PITCHB + seg) =
                *(const float4*)(g_zhi + (size_t)(m0 + row) * 64 + kk + seg);
            *(float4*)(Alo + row * PITCHB + seg) =
                *(const float4*)(g_zlo + (size_t)(m0 + row) * 64 + kk + seg);
            *(float4*)(Bhi + row * PITCHB + seg) =
                *(const float4*)(g_zhi + (size_t)(n0 + row) * 64 + kk + seg);
            *(float4*)(Blo + row * PITCHB + seg) =
                *(const float4*)(g_zlo + (size_t)(n0 + row) * 64 + kk + seg);
        }
        __syncthreads();
#pragma unroll
        for (int ks = 0; ks < 32; ks += 16) {
            uint32_t ahi[4][4], alo[4][4];
#pragma unroll
            for (int mt = 0; mt < 4; mt++) {
                int r = wm * 64 + mt * 16 + g;
                const __nv_bfloat16* p = Ahi + r * PITCHB + ks + 2 * t;
                ahi[mt][0] = *(const uint32_t*)(p);
                ahi[mt][1] = *(const uint32_t*)(p + 8 * PITCHB);
                ahi[mt][2] = *(const uint32_t*)(p + 8);
                ahi[mt][3] = *(const uint32_t*)(p + 8 * PITCHB + 8);
                const __nv_bfloat16* q = Alo + r * PITCHB + ks + 2 * t;
                alo[mt][0] = *(const uint32_t*)(q);
                alo[mt][1] = *(const uint32_t*)(q + 8 * PITCHB);
                alo[mt][2] = *(const uint32_t*)(q + 8);
                alo[mt][3] = *(const uint32_t*)(q + 8 * PITCHB + 8);
            }
#pragma unroll
            for (int nt = 0; nt < 4; nt++) {
                int n = wn * 32 + nt * 8 + g;
                const __nv_bfloat16* p = Bhi + n * PITCHB + ks + 2 * t;
                uint32_t bh0 = *(const uint32_t*)(p);
                uint32_t bh1 = *(const uint32_t*)(p + 8);
                const __nv_bfloat16* q = Blo + n * PITCHB + ks + 2 * t;
                uint32_t bl0 = *(const uint32_t*)(q);
                uint32_t bl1 = *(const uint32_t*)(q + 8);
#pragma unroll
                for (int mt = 0; mt < 4; mt++) {
                    mma_bf16(acc[mt][nt], ahi[mt], bh0, bh1);
                    mma_bf16(acc[mt][nt], ahi[mt], bl0, bl1);
                    mma_bf16(acc[mt][nt], alo[mt], bh0, bh1);
                }
            }
        }
    }

#pragma unroll
    for (int mt = 0; mt < 4; mt++)
#pragma unroll
        for (int nt = 0; nt < 4; nt++)
#pragma unroll
            for (int r = 0; r < 4; r++)
                acc[mt][nt][r] = 1.0f / (1.0f + __expf(-acc[mt][nt][r]));

#pragma unroll
    for (int mt = 0; mt < 4; mt++) {
        int r0 = m0 + wm * 64 + mt * 16 + g;
#pragma unroll
        for (int nt = 0; nt < 4; nt++) {
            int col = n0 + wn * 32 + nt * 8 + 2 * t;
            *(float2*)(out + (size_t)r0 * NN + col) =
                make_float2(acc[mt][nt][0], acc[mt][nt][1]);
            *(float2*)(out + (size_t)(r0 + 8) * NN + col) =
                make_float2(acc[mt][nt][2], acc[mt][nt][3]);
        }
    }
    if (bj == bi) return;

    float* st = (float*)smbuf;   // [64][136]
#pragma unroll
    for (int h = 0; h < 2; h++) {
        __syncthreads();
        if ((wn >> 1) == h) {
            int clbase = (wn & 1) * 32;
#pragma unroll
            for (int mt = 0; mt < 4; mt++) {
                int row = wm * 64 + mt * 16 + g;
#pragma unroll
                for (int nt = 0; nt < 4; nt++) {
                    int cl = clbase + nt * 8 + 2 * t;
                    st[cl * 136 + row]           = acc[mt][nt][0];
                    st[(cl + 1) * 136 + row]     = acc[mt][nt][1];
                    st[cl * 136 + row + 8]       = acc[mt][nt][2];
                    st[(cl + 1) * 136 + row + 8] = acc[mt][nt][3];
                }
            }
        }
        __syncthreads();
#pragma unroll
        for (int p = 0; p < 8; p++) {
            int lin = p * 256 + tid;
            int j  = lin >> 5;
            int iq = lin & 31;
            float4 v = *(const float4*)(st + j * 136 + iq * 4);
            *(float4*)(out + (size_t)(n0 + h * 64 + j) * NN + m0 + iq * 4) = v;
        }
    }
}

// ---------------------------------------------------------
extern "C" void kernel_launch(void* const* d_in, const int* in_sizes, int n_in,
                              void* d_out, int out_size) {
    const float* x     = (const float*)d_in[0];
    const int*   ei    = (const int*)d_in[1];
    const int*   batch = (const int*)d_in[2];
    const float* gw    = (const float*)d_in[3];
    const float* gb    = (const float*)d_in[4];
    const float* lw    = (const float*)d_in[5];
    const float* lb    = (const float*)d_in[6];
    const float* dw    = (const float*)d_in[7];
    const float* db    = (const float*)d_in[8];

    float* out     = (float*)d_out;
    float* z_node  = out;
    float* z_graph = out + NN * CLAT;
    float* x_hat   = z_graph + NG * CLAT;
    float* a_hat   = x_hat + NN * CIN;

    k_init<<<64, 256>>>();
    k_deg<<<NE / 256, 256>>>(ei);
    k_dinv<<<NN / 256, 256>>>();
    k_prefix<<<1, 1024>>>();
    k_place<<<NE / 256, 256>>>(ei);
    k_wT<<<(CIN * CHID + CHID * CLAT) / 256 + 1, 256>>>(gw, lw);
    k_gather<<<NN, 128>>>(x);
    k_gcn<<<NN / 4, 256>>>(gb);
    k_z<<<NN / 4, 256>>>(batch, lb, z_node);
    k_split<<<NN * CLAT / 256, 256>>>(z_node);
    k_graph<<<NG, 128>>>(dw, db, z_graph);
    k_xhat<<<NN * CIN / 256, 256>>>(batch, x_hat);

    dim3 grid(128, 128);
    k_ahat<<<grid, 256>>>(a_hat);
}

// round 12
// speedup vs baseline: 1.6438x; 1.6438x over previous
#include <cuda_runtime.h>
#include <cuda_bf16.h>
#include <cstdint>

#define NN   16384
#define NE   262144
#define NG   16
#define CIN  128
#define CHID 256
#define CLAT 64

// ---- scratch (device globals; no allocation allowed) ----
__device__ float g_deg[NN];
__device__ float g_dinv[NN];
__device__ float g_aggx[NN * CIN];
__device__ float g_h[NN * CHID];
__device__ float g_wT[CIN * CHID];
__device__ float g_linT[CHID * CLAT];
__device__ float g_zsum[NG * CLAT];
__device__ float g_cnt[NG];
__device__ float g_gdec[NG * CIN];
__device__ __nv_bfloat16 g_zhi[NN * CLAT];   // bf16 hi part of z_node
__device__ __nv_bfloat16 g_zlo[NN * CLAT];   // bf16 lo part of z_node

// ---------------------------------------------------------
__global__ void k_init() {
    int i = blockIdx.x * blockDim.x + threadIdx.x;
    if (i < NN) g_deg[i] = 1.0f;
    if (i < NG * CLAT) g_zsum[i] = 0.0f;
    if (i < NG) g_cnt[i] = 0.0f;
}

__global__ void k_deg(const int* __restrict__ ei) {
    int e = blockIdx.x * blockDim.x + threadIdx.x;
    if (e < NE) atomicAdd(&g_deg[ei[NE + e]], 1.0f);
}

__global__ void k_dinv() {
    int i = blockIdx.x * blockDim.x + threadIdx.x;
    if (i < NN) g_dinv[i] = rsqrtf(g_deg[i]);
}

__global__ void k_self(const float* __restrict__ x) {
    int idx = blockIdx.x * blockDim.x + threadIdx.x;
    if (idx < NN * CIN) g_aggx[idx] = x[idx] / g_deg[idx >> 7];
}

__global__ void k_scatter(const float4* __restrict__ x4, const int* __restrict__ ei) {
    int gt = blockIdx.x * blockDim.x + threadIdx.x;
    int e = gt >> 5;
    int lane = gt & 31;
    if (e >= NE) return;
    int row = ei[e];
    int col = ei[NE + e];
    float norm = g_dinv[row] * g_dinv[col];
    float4 v = x4[row * 32 + lane];
    v.x *= norm; v.y *= norm; v.z *= norm; v.w *= norm;
    float* dst = &g_aggx[(col * 32 + lane) * 4];
    asm volatile("red.global.add.v4.f32 [%0], {%1, %2, %3, %4};"
                 :: "l"(dst), "f"(v.x), "f"(v.y), "f"(v.z), "f"(v.w) : "memory");
}

__global__ void k_wT(const float* __restrict__ gw, const float* __restrict__ lw) {
    int idx = blockIdx.x * blockDim.x + threadIdx.x;
    if (idx < CIN * CHID) {
        int h = idx >> 7, k = idx & 127;
        g_wT[k * CHID + h] = gw[idx];
    } else if (idx < CIN * CHID + CHID * CLAT) {
        int j = idx - CIN * CHID;
        int l = j >> 8, c = j & 255;
        g_linT[c * CLAT + l] = lw[j];
    }
}

__global__ void k_gcn(const float* __restrict__ gb) {
    __shared__ float sx[4][CIN];
    int i0 = blockIdx.x * 4;
    int t = threadIdx.x;
#pragma unroll
    for (int ii = 0; ii < 2; ii++) {
        int lin = t + ii * 256;
        sx[lin >> 7][lin & 127] = g_aggx[i0 * CIN + lin];
    }
    __syncthreads();
    float b = gb[t];
    float a0 = b, a1 = b, a2 = b, a3 = b;
#pragma unroll 4
    for (int k = 0; k < CIN; k++) {
        float w = g_wT[k * CHID + t];
        a0 += sx[0][k] * w;
        a1 += sx[1][k] * w;
        a2 += sx[2][k] * w;
        a3 += sx[3][k] * w;
    }
    g_h[(i0 + 0) * CHID + t] = fmaxf(a0, 0.f);
    g_h[(i0 + 1) * CHID + t] = fmaxf(a1, 0.f);
    g_h[(i0 + 2) * CHID + t] = fmaxf(a2, 0.f);
    g_h[(i0 + 3) * CHID + t] = fmaxf(a3, 0.f);
}

__global__ void k_z(const int* __restrict__ batch, const float* __restrict__ lb,
                    float* __restrict__ zout) {
    __shared__ float sA[4][CHID];
    int i0 = blockIdx.x * 4;
    int t = threadIdx.x;
#pragma unroll
    for (int ii = 0; ii < 4; ii++) {
        int lin = t + ii * 256;
        sA[lin >> 8][lin & 255] = g_h[i0 * CHID + lin];
    }
    __syncthreads();
    int j = t >> 6, c = t & 63;
    float acc = lb[c];
#pragma unroll 4
    for (int k = 0; k < CHID; k++) acc += sA[j][k] * g_linT[k * CLAT + c];
    int node = i0 + j;
    zout[node * CLAT + c] = acc;
    int b = batch[node];
    atomicAdd(&g_zsum[b * CLAT + c], acc);
    if (c == 0) atomicAdd(&g_cnt[b], 1.0f);
}

// split z into bf16 hi + bf16 lo
__global__ void k_split(const float* __restrict__ z) {
    int i = blockIdx.x * blockDim.x + threadIdx.x;
    if (i < NN * CLAT) {
        float v = z[i];
        __nv_bfloat16 h = __float2bfloat16(v);
        float lo = v - __bfloat162float(h);
        g_zhi[i] = h;
        g_zlo[i] = __float2bfloat16(lo);
    }
}

__global__ void k_graph(const float* __restrict__ dw, const float* __restrict__ db,
                        float* __restrict__ zg_out) {
    __shared__ float zg[CLAT];
    int g = blockIdx.x, t = threadIdx.x;
    if (t < CLAT) {
        float cn = fmaxf(g_cnt[g], 1.0f);
        float v = g_zsum[g * CLAT + t] / cn;
        zg[t] = v;
        zg_out[g * CLAT + t] = v;
    }
    __syncthreads();
    float acc = db[t];
#pragma unroll
    for (int l = 0; l < CLAT; l++) acc += zg[l] * dw[t * CLAT + l];
    g_gdec[g * CIN + t] = acc;
}

__global__ void k_xhat(const int* __restrict__ batch, float* __restrict__ xo) {
    int idx = blockIdx.x * blockDim.x + threadIdx.x;
    if (idx < NN * CIN) {
        int i = idx >> 7;
        xo[idx] = g_gdec[batch[i] * CIN + (idx & 127)];
    }
}

// ---------------------------------------------------------
// a_hat = sigmoid(Z Z^T): split-bf16 mma.sync m16n8k16, 3 passes,
// ldmatrix fragment loads, approx-div sigmoid.
// ---------------------------------------------------------
__device__ __forceinline__ void mma_bf16(float* c, const uint32_t* a,
                                         uint32_t b0, uint32_t b1) {
    asm volatile(
        "mma.sync.aligned.m16n8k16.row.col.f32.bf16.bf16.f32 "
        "{%0,%1,%2,%3}, {%4,%5,%6,%7}, {%8,%9}, {%0,%1,%2,%3};"
        : "+f"(c[0]), "+f"(c[1]), "+f"(c[2]), "+f"(c[3])
        : "r"(a[0]), "r"(a[1]), "r"(a[2]), "r"(a[3]), "r"(b0), "r"(b1));
}
__device__ __forceinline__ void ldsm_x4(uint32_t* r, uint32_t addr) {
    asm volatile("ldmatrix.sync.aligned.m8n8.x4.shared.b16 {%0,%1,%2,%3}, [%4];"
                 : "=r"(r[0]), "=r"(r[1]), "=r"(r[2]), "=r"(r[3]) : "r"(addr));
}
__device__ __forceinline__ uint32_t smem_u32(const void* p) {
    return (uint32_t)__cvta_generic_to_shared(p);
}

#define PITCHB 40

__global__ void __launch_bounds__(256) k_ahat(float* __restrict__ out) {
    __shared__ __align__(16) char smbuf[4 * 128 * PITCHB * 2];  // 40960 B
    __nv_bfloat16* Ahi = (__nv_bfloat16*)smbuf;
    __nv_bfloat16* Alo = Ahi + 128 * PITCHB;
    __nv_bfloat16* Bhi = Alo + 128 * PITCHB;
    __nv_bfloat16* Blo = Bhi + 128 * PITCHB;

    const int bi = blockIdx.y, bj = blockIdx.x;
    if (bj < bi) return;
    const int tid  = threadIdx.x;
    const int w    = tid >> 5, lane = tid & 31;
    const int wm   = w & 1, wn = w >> 1;
    const int g    = lane >> 2, t = lane & 3;
    const int m0 = bi * 128, n0 = bj * 128;

    // ldmatrix lane-address offsets (in elements)
    const int lr = lane & 7, lq = lane >> 3;
    const int a_ro = ((lq & 1) << 3) + lr;       // row offset for A frags
    const int a_co = (lq >> 1) << 3;             // col offset for A frags
    const int b_ro = ((lq >> 1) << 3) + lr;      // row offset for B frag pairs
    const int b_co = (lq & 1) << 3;              // col offset for B frag pairs

    const uint32_t uAhi = smem_u32(Ahi), uAlo = smem_u32(Alo);
    const uint32_t uBhi = smem_u32(Bhi), uBlo = smem_u32(Blo);

    float acc[4][4][4];
#pragma unroll
    for (int a = 0; a < 4; a++)
#pragma unroll
        for (int b = 0; b < 4; b++)
#pragma unroll
            for (int r = 0; r < 4; r++) acc[a][b][r] = 0.f;

#pragma unroll
    for (int kk = 0; kk < 64; kk += 32) {
        __syncthreads();
#pragma unroll
        for (int i = 0; i < 2; i++) {
            int lin = tid + i * 256;
            int row = lin >> 2;
            int seg = (lin & 3) * 8;
            *(float4*)(Ahi + row * PITCHB + seg) =
                *(const float4*)(g_zhi + (size_t)(m0 + row) * 64 + kk + seg);
            *(float4*)(Alo + row * PITCHB + seg) =
                *(const float4*)(g_zlo + (size_t)(m0 + row) * 64 + kk + seg);
            *(float4*)(Bhi + row * PITCHB + seg) =
                *(const float4*)(g_zhi + (size_t)(n0 + row) * 64 + kk + seg);
            *(float4*)(Blo + row * PITCHB + seg) =
                *(const float4*)(g_zlo + (size_t)(n0 + row) * 64 + kk + seg);
        }
        __syncthreads();
#pragma unroll
        for (int ks = 0; ks < 32; ks += 16) {
            uint32_t ahi[4][4], alo[4][4];
#pragma unroll
            for (int mt = 0; mt < 4; mt++) {
                uint32_t eoff =
                    (uint32_t)((wm * 64 + mt * 16 + a_ro) * PITCHB + ks + a_co) * 2;
                ldsm_x4(ahi[mt], uAhi + eoff);
                ldsm_x4(alo[mt], uAlo + eoff);
            }
            uint32_t bhi[4][2], blo[4][2];
#pragma unroll
            for (int ntp = 0; ntp < 2; ntp++) {
                uint32_t eoff =
                    (uint32_t)((wn * 32 + ntp * 16 + b_ro) * PITCHB + ks + b_co) * 2;
                uint32_t rh[4], rl[4];
                ldsm_x4(rh, uBhi + eoff);
                ldsm_x4(rl, uBlo + eoff);
                bhi[ntp * 2][0] = rh[0]; bhi[ntp * 2][1] = rh[1];
                bhi[ntp * 2 + 1][0] = rh[2]; bhi[ntp * 2 + 1][1] = rh[3];
                blo[ntp * 2][0] = rl[0]; blo[ntp * 2][1] = rl[1];
                blo[ntp * 2 + 1][0] = rl[2]; blo[ntp * 2 + 1][1] = rl[3];
            }
#pragma unroll
            for (int nt = 0; nt < 4; nt++) {
#pragma unroll
                for (int mt = 0; mt < 4; mt++) {
                    mma_bf16(acc[mt][nt], ahi[mt], bhi[nt][0], bhi[nt][1]);
                    mma_bf16(acc[mt][nt], ahi[mt], blo[nt][0], blo[nt][1]);
                    mma_bf16(acc[mt][nt], alo[mt], bhi[nt][0], bhi[nt][1]);
                }
            }
        }
    }

    // sigmoid (approx div: MUFU.RCP, no Newton chain)
#pragma unroll
    for (int mt = 0; mt < 4; mt++)
#pragma unroll
        for (int nt = 0; nt < 4; nt++)
#pragma unroll
            for (int r = 0; r < 4; r++)
                acc[mt][nt][r] = __fdividef(1.0f, 1.0f + __expf(-acc[mt][nt][r]));

#pragma unroll
    for (int mt = 0; mt < 4; mt++) {
        int r0 = m0 + wm * 64 + mt * 16 + g;
#pragma unroll
        for (int nt = 0; nt < 4; nt++) {
            int col = n0 + wn * 32 + nt * 8 + 2 * t;
            *(float2*)(out + (size_t)r0 * NN + col) =
                make_float2(acc[mt][nt][0], acc[mt][nt][1]);
            *(float2*)(out + (size_t)(r0 + 8) * NN + col) =
                make_float2(acc[mt][nt][2], acc[mt][nt][3]);
        }
    }
    if (bj == bi) return;

    float* st = (float*)smbuf;   // [64][136]
#pragma unroll
    for (int h = 0; h < 2; h++) {
        __syncthreads();
        if ((wn >> 1) == h) {
            int clbase = (wn & 1) * 32;
#pragma unroll
            for (int mt = 0; mt < 4; mt++) {
                int row = wm * 64 + mt * 16 + g;
#pragma unroll
                for (int nt = 0; nt < 4; nt++) {
                    int cl = clbase + nt * 8 + 2 * t;
                    st[cl * 136 + row]           = acc[mt][nt][0];
                    st[(cl + 1) * 136 + row]     = acc[mt][nt][1];
                    st[cl * 136 + row + 8]       = acc[mt][nt][2];
                    st[(cl + 1) * 136 + row + 8] = acc[mt][nt][3];
                }
            }
        }
        __syncthreads();
#pragma unroll
        for (int p = 0; p < 8; p++) {
            int lin = p * 256 + tid;
            int j  = lin >> 5;
            int iq = lin & 31;
            float4 v = *(const float4*)(st + j * 136 + iq * 4);
            *(float4*)(out + (size_t)(n0 + h * 64 + j) * NN + m0 + iq * 4) = v;
        }
    }
}

// ---------------------------------------------------------
extern "C" void kernel_launch(void* const* d_in, const int* in_sizes, int n_in,
                              void* d_out, int out_size) {
    const float* x     = (const float*)d_in[0];
    const int*   ei    = (const int*)d_in[1];
    const int*   batch = (const int*)d_in[2];
    const float* gw    = (const float*)d_in[3];
    const float* gb    = (const float*)d_in[4];
    const float* lw    = (const float*)d_in[5];
    const float* lb    = (const float*)d_in[6];
    const float* dw    = (const float*)d_in[7];
    const float* db    = (const float*)d_in[8];

    float* out     = (float*)d_out;
    float* z_node  = out;
    float* z_graph = out + NN * CLAT;
    float* x_hat   = z_graph + NG * CLAT;
    float* a_hat   = x_hat + NN * CIN;

    k_init<<<64, 256>>>();
    k_deg<<<NE / 256, 256>>>(ei);
    k_dinv<<<NN / 256, 256>>>();
    k_self<<<NN * CIN / 256, 256>>>(x);
    k_wT<<<(CIN * CHID + CHID * CLAT) / 256 + 1, 256>>>(gw, lw);
    k_scatter<<<NE * 32 / 256, 256>>>((const float4*)x, ei);
    k_gcn<<<NN / 4, 256>>>(gb);
    k_z<<<NN / 4, 256>>>(batch, lb, z_node);
    k_split<<<NN * CLAT / 256, 256>>>(z_node);
    k_graph<<<NG, 128>>>(dw, db, z_graph);
    k_xhat<<<NN * CIN / 256, 256>>>(batch, x_hat);

    dim3 grid(128, 128);
    k_ahat<<<grid, 256>>>(a_hat);
}